// round 1
// baseline (speedup 1.0000x reference)
#include <cuda_runtime.h>
#include <math.h>

// Problem constants
#define BHW   4096            // H*W
#define CCH   256             // channels
#define NBAT  4               // batch
#define NTOK  16384           // NBAT*BHW
#define NGRP  32
#define CPG   8               // channels per group
#define GELEMS (CPG*BHW)      // 32768 elems per (b,g)
#define OUT_MAIN ((size_t)NBAT*CCH*BHW)   // offset of u_map in d_out

// ---------------- scratch (__device__ globals; no allocation allowed) --------
__device__ float g_t[(size_t)NTOK*CCH];   // normalized tokens [tok, c]
__device__ float g_q[(size_t)NTOK*CCH];
__device__ float g_k[(size_t)NTOK*CCH];
__device__ float g_v[(size_t)NTOK*CCH];
__device__ float g_o[(size_t)NTOK*CCH];   // attn output [tok, c]
__device__ float g_y[(size_t)NTOK*CCH];   // proj output [tok, c]
__device__ float g_u[NTOK];               // sigmoid gate
__device__ float g_mu[NBAT*NGRP];
__device__ float g_rs[NBAT*NGRP];
__device__ float g_s[(size_t)NBAT*BHW*BHW]; // scores / probs, 256 MB

// ---------------- GroupNorm stats -------------------------------------------
__global__ void gn_stats(const float* __restrict__ x) {
    int bg = blockIdx.x;                       // b*32 + g ; group data contiguous
    const float4* p = (const float4*)(x + (size_t)bg * GELEMS);
    float s = 0.f, ss = 0.f;
    for (int i = threadIdx.x; i < GELEMS/4; i += blockDim.x) {
        float4 v = p[i];
        s  += v.x + v.y + v.z + v.w;
        ss += v.x*v.x + v.y*v.y + v.z*v.z + v.w*v.w;
    }
    __shared__ float rs[8], rss[8];
    #pragma unroll
    for (int o = 16; o; o >>= 1) { s += __shfl_down_sync(~0u, s, o); ss += __shfl_down_sync(~0u, ss, o); }
    if ((threadIdx.x & 31) == 0) { rs[threadIdx.x >> 5] = s; rss[threadIdx.x >> 5] = ss; }
    __syncthreads();
    if (threadIdx.x < 32) {
        s  = (threadIdx.x < 8) ? rs[threadIdx.x]  : 0.f;
        ss = (threadIdx.x < 8) ? rss[threadIdx.x] : 0.f;
        #pragma unroll
        for (int o = 4; o; o >>= 1) { s += __shfl_down_sync(~0u, s, o); ss += __shfl_down_sync(~0u, ss, o); }
        if (threadIdx.x == 0) {
            float mu  = s / (float)GELEMS;
            float var = ss / (float)GELEMS - mu * mu;
            g_mu[bg] = mu;
            g_rs[bg] = rsqrtf(var + 1e-6f);
        }
    }
}

// ---------------- normalize + transpose to [tok, c] --------------------------
__global__ void gn_apply(const float* __restrict__ x,
                         const float* __restrict__ gamma,
                         const float* __restrict__ beta) {
    __shared__ float tile[32][33];
    int b  = blockIdx.z;
    int c0 = blockIdx.y * 32;
    int s0 = blockIdx.x * 32;
    int tx = threadIdx.x, ty = threadIdx.y;
    for (int i = ty; i < 32; i += 8) {
        int c = c0 + i;
        int bg = b * NGRP + (c >> 3);
        float v = x[((size_t)(b * CCH + c)) * BHW + s0 + tx];
        tile[i][tx] = (v - g_mu[bg]) * g_rs[bg] * gamma[c] + beta[c];
    }
    __syncthreads();
    for (int i = ty; i < 32; i += 8)
        g_t[((size_t)(b * BHW + s0 + i)) * CCH + c0 + tx] = tile[tx][i];
}

// ---------------- tf32 mma helpers -------------------------------------------
__device__ __forceinline__ unsigned f2tf(float f) {
    unsigned r; asm("cvt.rna.tf32.f32 %0, %1;" : "=r"(r) : "f"(f)); return r;
}
__device__ __forceinline__ void mma_tf32(float* c, const unsigned* a, const unsigned* b) {
    asm volatile("mma.sync.aligned.m16n8k8.row.col.f32.tf32.tf32.f32 "
                 "{%0,%1,%2,%3}, {%4,%5,%6,%7}, {%8,%9}, {%0,%1,%2,%3};"
                 : "+f"(c[0]), "+f"(c[1]), "+f"(c[2]), "+f"(c[3])
                 : "r"(a[0]), "r"(a[1]), "r"(a[2]), "r"(a[3]), "r"(b[0]), "r"(b[1]));
}

// Generic 128x128-tile GEMM, K multiple of 32, M,N multiples of 128.
//   C[M,N] = A[M,K] @ B  (+epilogue)
// BLAYOUT 0: B given as W[N,K] row-major (i.e. C = A @ W^T)
// BLAYOUT 1: B given as B[K,N] row-major (i.e. C = A @ B)
// EPI 0: +bias[n]    EPI 1: *uscale*uvec[n]   EPI 2: plain
template<int BLAYOUT, int EPI>
__global__ __launch_bounds__(256)
void gemm_tf32(const float* __restrict__ A, const float* __restrict__ Bm,
               float* __restrict__ Cp, int N, int K,
               const float* __restrict__ bias, const float* __restrict__ uvec,
               float uscale, size_t sA, size_t sB, size_t sC, size_t sU) {
    int bz = blockIdx.z;
    A  += (size_t)bz * sA;
    Bm += (size_t)bz * sB;
    Cp += (size_t)bz * sC;
    if (EPI == 1) uvec += (size_t)bz * sU;

    const int m0 = blockIdx.y * 128;
    const int n0 = blockIdx.x * 128;
    const int tid  = threadIdx.x;
    const int lane = tid & 31;
    const int warp = tid >> 5;
    const int wm = warp >> 1;      // 0..3  (M tiles of 32)
    const int wn = warp & 1;       // 0..1  (N tiles of 64)
    const int g  = lane >> 2;      // groupID
    const int t4 = lane & 3;       // threadID_in_group

    __shared__ float As[128 * 36];
    __shared__ float Bs[BLAYOUT == 1 ? 32 * 136 : 128 * 36];

    float acc[2][8][4];
    #pragma unroll
    for (int mi = 0; mi < 2; mi++)
        #pragma unroll
        for (int ni = 0; ni < 8; ni++)
            #pragma unroll
            for (int e = 0; e < 4; e++) acc[mi][ni][e] = 0.f;

    for (int kc = 0; kc < K; kc += 32) {
        // stage A tile [128 x 32]
        #pragma unroll
        for (int it = 0; it < 4; it++) {
            int idx = tid + it * 256;
            int row = idx >> 3, seg = idx & 7;
            float4 v = *(const float4*)(A + (size_t)(m0 + row) * K + kc + seg * 4);
            *(float4*)(As + row * 36 + seg * 4) = v;
        }
        if (BLAYOUT == 0) {
            #pragma unroll
            for (int it = 0; it < 4; it++) {
                int idx = tid + it * 256;
                int row = idx >> 3, seg = idx & 7;
                float4 v = *(const float4*)(Bm + (size_t)(n0 + row) * K + kc + seg * 4);
                *(float4*)(Bs + row * 36 + seg * 4) = v;
            }
        } else {
            #pragma unroll
            for (int it = 0; it < 4; it++) {
                int idx = tid + it * 256;
                int row = idx >> 5, seg = idx & 31;
                float4 v = *(const float4*)(Bm + (size_t)(kc + row) * N + n0 + seg * 4);
                *(float4*)(Bs + row * 136 + seg * 4) = v;
            }
        }
        __syncthreads();

        #pragma unroll
        for (int ks = 0; ks < 4; ks++) {
            const int k0 = ks * 8;
            unsigned af[2][4];
            #pragma unroll
            for (int mi = 0; mi < 2; mi++) {
                int r = wm * 32 + mi * 16 + g;
                af[mi][0] = f2tf(As[r * 36 + k0 + t4]);
                af[mi][1] = f2tf(As[(r + 8) * 36 + k0 + t4]);
                af[mi][2] = f2tf(As[r * 36 + k0 + t4 + 4]);
                af[mi][3] = f2tf(As[(r + 8) * 36 + k0 + t4 + 4]);
            }
            unsigned bf[8][2];
            #pragma unroll
            for (int ni = 0; ni < 8; ni++) {
                int ccol = wn * 64 + ni * 8 + g;
                if (BLAYOUT == 0) {
                    bf[ni][0] = f2tf(Bs[ccol * 36 + k0 + t4]);
                    bf[ni][1] = f2tf(Bs[ccol * 36 + k0 + t4 + 4]);
                } else {
                    bf[ni][0] = f2tf(Bs[(k0 + t4) * 136 + ccol]);
                    bf[ni][1] = f2tf(Bs[(k0 + t4 + 4) * 136 + ccol]);
                }
            }
            #pragma unroll
            for (int mi = 0; mi < 2; mi++)
                #pragma unroll
                for (int ni = 0; ni < 8; ni++)
                    mma_tf32(acc[mi][ni], af[mi], bf[ni]);
        }
        __syncthreads();
    }

    // epilogue: float2 stores, 32B contiguous per quad per row
    #pragma unroll
    for (int mi = 0; mi < 2; mi++) {
        int rbase = m0 + wm * 32 + mi * 16 + g;
        #pragma unroll
        for (int ni = 0; ni < 8; ni++) {
            int cc = n0 + wn * 64 + ni * 8 + t4 * 2;
            #pragma unroll
            for (int half = 0; half < 2; half++) {
                int rr = rbase + half * 8;
                float v0 = acc[mi][ni][half * 2 + 0];
                float v1 = acc[mi][ni][half * 2 + 1];
                if (EPI == 0) { v0 += bias[cc]; v1 += bias[cc + 1]; }
                else if (EPI == 1) { v0 *= uscale * uvec[cc]; v1 *= uscale * uvec[cc + 1]; }
                float2 w; w.x = v0; w.y = v1;
                *(float2*)(Cp + (size_t)rr * N + cc) = w;
            }
        }
    }
}

// ---------------- u = sigmoid(t @ wu^T + bu) ---------------------------------
__global__ void u_kernel(const float* __restrict__ wu, const float* __restrict__ bu,
                         float* __restrict__ dout_u) {
    int i = blockIdx.x * 8 + (threadIdx.x >> 5);
    int lane = threadIdx.x & 31;
    const float* t = g_t + (size_t)i * CCH;
    float s = 0.f;
    #pragma unroll
    for (int j = 0; j < 8; j++) s += t[lane + j * 32] * wu[lane + j * 32];
    #pragma unroll
    for (int o = 16; o; o >>= 1) s += __shfl_down_sync(~0u, s, o);
    if (lane == 0) {
        float uu = 1.f / (1.f + expf(-(s + bu[0])));
        g_u[i] = uu;
        dout_u[i] = uu;
    }
}

// ---------------- row softmax over 4096 keys ---------------------------------
__global__ void softmax_rows(float* __restrict__ S) {
    float4* p = (float4*)(S + (size_t)blockIdx.x * BHW);
    int tid = threadIdx.x;
    __shared__ float red[8];
    float m = -1e30f;
    for (int j = tid; j < BHW / 4; j += 256) {
        float4 v = p[j];
        m = fmaxf(fmaxf(fmaxf(m, v.x), v.y), fmaxf(v.z, v.w));
    }
    #pragma unroll
    for (int o = 16; o; o >>= 1) m = fmaxf(m, __shfl_xor_sync(~0u, m, o));
    if ((tid & 31) == 0) red[tid >> 5] = m;
    __syncthreads();
    m = fmaxf(fmaxf(fmaxf(red[0], red[1]), fmaxf(red[2], red[3])),
              fmaxf(fmaxf(red[4], red[5]), fmaxf(red[6], red[7])));
    __syncthreads();
    float s = 0.f;
    for (int j = tid; j < BHW / 4; j += 256) {
        float4 v = p[j];
        v.x = __expf(v.x - m); v.y = __expf(v.y - m);
        v.z = __expf(v.z - m); v.w = __expf(v.w - m);
        s += v.x + v.y + v.z + v.w;
        p[j] = v;
    }
    #pragma unroll
    for (int o = 16; o; o >>= 1) s += __shfl_xor_sync(~0u, s, o);
    if ((tid & 31) == 0) red[tid >> 5] = s;
    __syncthreads();
    s = red[0] + red[1] + red[2] + red[3] + red[4] + red[5] + red[6] + red[7];
    float inv = 1.f / s;
    for (int j = tid; j < BHW / 4; j += 256) {
        float4 v = p[j];
        v.x *= inv; v.y *= inv; v.z *= inv; v.w *= inv;
        p[j] = v;
    }
}

// ---------------- final: out = x + y^T (per batch), transpose ----------------
__global__ void final_out(const float* __restrict__ x, float* __restrict__ out) {
    __shared__ float tile[32][33];
    int b  = blockIdx.z;
    int c0 = blockIdx.y * 32;
    int s0 = blockIdx.x * 32;
    int tx = threadIdx.x, ty = threadIdx.y;
    for (int i = ty; i < 32; i += 8)
        tile[i][tx] = g_y[((size_t)(b * BHW + s0 + i)) * CCH + c0 + tx];
    __syncthreads();
    for (int i = ty; i < 32; i += 8) {
        size_t idx = ((size_t)(b * CCH + c0 + i)) * BHW + s0 + tx;
        out[idx] = x[idx] + tile[tx][i];
    }
}

// ---------------- launch -----------------------------------------------------
extern "C" void kernel_launch(void* const* d_in, const int* in_sizes, int n_in,
                              void* d_out, int out_size) {
    (void)in_sizes; (void)n_in; (void)out_size;
    const float* x     = (const float*)d_in[0];
    const float* gamma = (const float*)d_in[1];
    const float* beta  = (const float*)d_in[2];
    const float* wq    = (const float*)d_in[3];
    const float* bq    = (const float*)d_in[4];
    const float* wk    = (const float*)d_in[5];
    const float* bk    = (const float*)d_in[6];
    const float* wv    = (const float*)d_in[7];
    const float* bv    = (const float*)d_in[8];
    const float* wu    = (const float*)d_in[9];
    const float* bu    = (const float*)d_in[10];
    const float* wp    = (const float*)d_in[11];
    const float* bp    = (const float*)d_in[12];
    float* out = (float*)d_out;

    float *pt, *pq, *pk, *pv, *po, *py, *pu, *ps;
    cudaGetSymbolAddress((void**)&pt, g_t);
    cudaGetSymbolAddress((void**)&pq, g_q);
    cudaGetSymbolAddress((void**)&pk, g_k);
    cudaGetSymbolAddress((void**)&pv, g_v);
    cudaGetSymbolAddress((void**)&po, g_o);
    cudaGetSymbolAddress((void**)&py, g_y);
    cudaGetSymbolAddress((void**)&pu, g_u);
    cudaGetSymbolAddress((void**)&ps, g_s);

    // 1) GroupNorm
    gn_stats<<<NBAT * NGRP, 256>>>(x);
    gn_apply<<<dim3(BHW / 32, CCH / 32, NBAT), dim3(32, 8)>>>(x, gamma, beta);

    // 2) QKV projections: [16384,256] = t @ W^T + b
    gemm_tf32<0, 0><<<dim3(2, 128, 1), 256>>>(pt, wq, pq, 256, 256, bq, nullptr, 0.f, 0, 0, 0, 0);
    gemm_tf32<0, 0><<<dim3(2, 128, 1), 256>>>(pt, wk, pk, 256, 256, bk, nullptr, 0.f, 0, 0, 0, 0);
    gemm_tf32<0, 0><<<dim3(2, 128, 1), 256>>>(pt, wv, pv, 256, 256, bv, nullptr, 0.f, 0, 0, 0, 0);

    // 3) gate (also writes u_map part of output)
    u_kernel<<<NTOK / 8, 256>>>(wu, bu, out + OUT_MAIN);

    // 4) scores[b] = (q[b] @ k[b]^T) * scale * u[b, j]
    gemm_tf32<0, 1><<<dim3(32, 32, NBAT), 256>>>(pq, pk, ps, BHW, 256, nullptr, pu, 0.0625f,
                                                 (size_t)BHW * CCH, (size_t)BHW * CCH,
                                                 (size_t)BHW * BHW, (size_t)BHW);

    // 5) softmax over keys
    softmax_rows<<<NTOK, 256>>>(ps);

    // 6) out[b] = P[b] @ v[b]   (B non-transposed: [K=4096, N=256])
    gemm_tf32<1, 2><<<dim3(2, 32, NBAT), 256>>>(ps, pv, po, 256, BHW, nullptr, nullptr, 0.f,
                                                (size_t)BHW * BHW, (size_t)BHW * CCH,
                                                (size_t)BHW * CCH, 0);

    // 7) projection
    gemm_tf32<0, 0><<<dim3(2, 128, 1), 256>>>(po, wp, py, 256, 256, bp, nullptr, 0.f, 0, 0, 0, 0);

    // 8) residual + transpose back to [B,C,H,W]
    final_out<<<dim3(BHW / 32, CCH / 32, NBAT), dim3(32, 8)>>>(x, out);
}

// round 2
// speedup vs baseline: 1.0046x; 1.0046x over previous
#include <cuda_runtime.h>
#include <math.h>

// Problem constants
#define BHW   4096            // H*W
#define CCH   256             // channels
#define NBAT  4               // batch
#define NTOK  16384           // NBAT*BHW
#define NGRP  32
#define CPG   8               // channels per group
#define GELEMS (CPG*BHW)      // 32768 elems per (b,g)
#define OUT_MAIN ((size_t)NBAT*CCH*BHW)   // offset of u_map in d_out

// ---------------- scratch (__device__ globals; no allocation allowed) --------
__device__ float g_t[(size_t)NTOK*CCH];   // normalized tokens [tok, c]
__device__ float g_q[(size_t)NTOK*CCH];
__device__ float g_k[(size_t)NTOK*CCH];
__device__ float g_v[(size_t)NTOK*CCH];
__device__ float g_o[(size_t)NTOK*CCH];   // attn output [tok, c]
__device__ float g_y[(size_t)NTOK*CCH];   // proj output [tok, c]
__device__ float g_u[NTOK];               // sigmoid gate
__device__ float g_mu[NBAT*NGRP];
__device__ float g_rs[NBAT*NGRP];
__device__ float g_s[(size_t)NBAT*BHW*BHW]; // scores / probs, 256 MB

// ---------------- GroupNorm stats -------------------------------------------
__global__ void gn_stats(const float* __restrict__ x) {
    int bg = blockIdx.x;                       // b*32 + g ; group data contiguous
    const float4* p = (const float4*)(x + (size_t)bg * GELEMS);
    float s = 0.f, ss = 0.f;
    for (int i = threadIdx.x; i < GELEMS/4; i += blockDim.x) {
        float4 v = p[i];
        s  += v.x + v.y + v.z + v.w;
        ss += v.x*v.x + v.y*v.y + v.z*v.z + v.w*v.w;
    }
    __shared__ float rs[8], rss[8];
    #pragma unroll
    for (int o = 16; o; o >>= 1) { s += __shfl_down_sync(~0u, s, o); ss += __shfl_down_sync(~0u, ss, o); }
    if ((threadIdx.x & 31) == 0) { rs[threadIdx.x >> 5] = s; rss[threadIdx.x >> 5] = ss; }
    __syncthreads();
    if (threadIdx.x < 32) {
        s  = (threadIdx.x < 8) ? rs[threadIdx.x]  : 0.f;
        ss = (threadIdx.x < 8) ? rss[threadIdx.x] : 0.f;
        #pragma unroll
        for (int o = 4; o; o >>= 1) { s += __shfl_down_sync(~0u, s, o); ss += __shfl_down_sync(~0u, ss, o); }
        if (threadIdx.x == 0) {
            float mu  = s / (float)GELEMS;
            float var = ss / (float)GELEMS - mu * mu;
            g_mu[bg] = mu;
            g_rs[bg] = rsqrtf(var + 1e-6f);
        }
    }
}

// ---------------- normalize + transpose to [tok, c] --------------------------
__global__ void gn_apply(const float* __restrict__ x,
                         const float* __restrict__ gamma,
                         const float* __restrict__ beta) {
    __shared__ float tile[32][33];
    int b  = blockIdx.z;
    int c0 = blockIdx.y * 32;
    int s0 = blockIdx.x * 32;
    int tx = threadIdx.x, ty = threadIdx.y;
    for (int i = ty; i < 32; i += 8) {
        int c = c0 + i;
        int bg = b * NGRP + (c >> 3);
        float v = x[((size_t)(b * CCH + c)) * BHW + s0 + tx];
        tile[i][tx] = (v - g_mu[bg]) * g_rs[bg] * gamma[c] + beta[c];
    }
    __syncthreads();
    for (int i = ty; i < 32; i += 8)
        g_t[((size_t)(b * BHW + s0 + i)) * CCH + c0 + tx] = tile[tx][i];
}

// ---------------- tf32 mma helpers -------------------------------------------
__device__ __forceinline__ unsigned f2tf(float f) {
    unsigned r; asm("cvt.rna.tf32.f32 %0, %1;" : "=r"(r) : "f"(f)); return r;
}
__device__ __forceinline__ void mma_tf32(float* c, const unsigned* a, const unsigned* b) {
    asm volatile("mma.sync.aligned.m16n8k8.row.col.f32.tf32.tf32.f32 "
                 "{%0,%1,%2,%3}, {%4,%5,%6,%7}, {%8,%9}, {%0,%1,%2,%3};"
                 : "+f"(c[0]), "+f"(c[1]), "+f"(c[2]), "+f"(c[3])
                 : "r"(a[0]), "r"(a[1]), "r"(a[2]), "r"(a[3]), "r"(b[0]), "r"(b[1]));
}

// Generic 128x128-tile GEMM, K multiple of 32, M,N multiples of 128.
//   C[M,N] = A[M,K] @ B  (+epilogue)
// BLAYOUT 0: B given as W[N,K] row-major (i.e. C = A @ W^T)
// BLAYOUT 1: B given as B[K,N] row-major (i.e. C = A @ B)
// EPI 0: +bias[n]    EPI 1: *uscale*uvec[n]   EPI 2: plain
template<int BLAYOUT, int EPI>
__global__ __launch_bounds__(256)
void gemm_tf32(const float* __restrict__ A, const float* __restrict__ Bm,
               float* __restrict__ Cp, int N, int K,
               const float* __restrict__ bias, const float* __restrict__ uvec,
               float uscale, size_t sA, size_t sB, size_t sC, size_t sU) {
    int bz = blockIdx.z;
    A  += (size_t)bz * sA;
    Bm += (size_t)bz * sB;
    Cp += (size_t)bz * sC;
    if (EPI == 1) uvec += (size_t)bz * sU;

    const int m0 = blockIdx.y * 128;
    const int n0 = blockIdx.x * 128;
    const int tid  = threadIdx.x;
    const int lane = tid & 31;
    const int warp = tid >> 5;
    const int wm = warp >> 1;      // 0..3  (M tiles of 32)
    const int wn = warp & 1;       // 0..1  (N tiles of 64)
    const int g  = lane >> 2;      // groupID
    const int t4 = lane & 3;       // threadID_in_group

    __shared__ float As[128 * 36];
    __shared__ float Bs[BLAYOUT == 1 ? 32 * 136 : 128 * 36];

    float acc[2][8][4];
    #pragma unroll
    for (int mi = 0; mi < 2; mi++)
        #pragma unroll
        for (int ni = 0; ni < 8; ni++)
            #pragma unroll
            for (int e = 0; e < 4; e++) acc[mi][ni][e] = 0.f;

    for (int kc = 0; kc < K; kc += 32) {
        // stage A tile [128 x 32]
        #pragma unroll
        for (int it = 0; it < 4; it++) {
            int idx = tid + it * 256;
            int row = idx >> 3, seg = idx & 7;
            float4 v = *(const float4*)(A + (size_t)(m0 + row) * K + kc + seg * 4);
            *(float4*)(As + row * 36 + seg * 4) = v;
        }
        if (BLAYOUT == 0) {
            #pragma unroll
            for (int it = 0; it < 4; it++) {
                int idx = tid + it * 256;
                int row = idx >> 3, seg = idx & 7;
                float4 v = *(const float4*)(Bm + (size_t)(n0 + row) * K + kc + seg * 4);
                *(float4*)(Bs + row * 36 + seg * 4) = v;
            }
        } else {
            #pragma unroll
            for (int it = 0; it < 4; it++) {
                int idx = tid + it * 256;
                int row = idx >> 5, seg = idx & 31;
                float4 v = *(const float4*)(Bm + (size_t)(kc + row) * N + n0 + seg * 4);
                *(float4*)(Bs + row * 136 + seg * 4) = v;
            }
        }
        __syncthreads();

        #pragma unroll
        for (int ks = 0; ks < 4; ks++) {
            const int k0 = ks * 8;
            unsigned af[2][4];
            #pragma unroll
            for (int mi = 0; mi < 2; mi++) {
                int r = wm * 32 + mi * 16 + g;
                af[mi][0] = f2tf(As[r * 36 + k0 + t4]);
                af[mi][1] = f2tf(As[(r + 8) * 36 + k0 + t4]);
                af[mi][2] = f2tf(As[r * 36 + k0 + t4 + 4]);
                af[mi][3] = f2tf(As[(r + 8) * 36 + k0 + t4 + 4]);
            }
            unsigned bf[8][2];
            #pragma unroll
            for (int ni = 0; ni < 8; ni++) {
                int ccol = wn * 64 + ni * 8 + g;
                if (BLAYOUT == 0) {
                    bf[ni][0] = f2tf(Bs[ccol * 36 + k0 + t4]);
                    bf[ni][1] = f2tf(Bs[ccol * 36 + k0 + t4 + 4]);
                } else {
                    bf[ni][0] = f2tf(Bs[(k0 + t4) * 136 + ccol]);
                    bf[ni][1] = f2tf(Bs[(k0 + t4 + 4) * 136 + ccol]);
                }
            }
            #pragma unroll
            for (int mi = 0; mi < 2; mi++)
                #pragma unroll
                for (int ni = 0; ni < 8; ni++)
                    mma_tf32(acc[mi][ni], af[mi], bf[ni]);
        }
        __syncthreads();
    }

    // epilogue: float2 stores, 32B contiguous per quad per row
    #pragma unroll
    for (int mi = 0; mi < 2; mi++) {
        int rbase = m0 + wm * 32 + mi * 16 + g;
        #pragma unroll
        for (int ni = 0; ni < 8; ni++) {
            int cc = n0 + wn * 64 + ni * 8 + t4 * 2;
            #pragma unroll
            for (int half = 0; half < 2; half++) {
                int rr = rbase + half * 8;
                float v0 = acc[mi][ni][half * 2 + 0];
                float v1 = acc[mi][ni][half * 2 + 1];
                if (EPI == 0) { v0 += bias[cc]; v1 += bias[cc + 1]; }
                else if (EPI == 1) { v0 *= uscale * uvec[cc]; v1 *= uscale * uvec[cc + 1]; }
                float2 w; w.x = v0; w.y = v1;
                *(float2*)(Cp + (size_t)rr * N + cc) = w;
            }
        }
    }
}

// ---------------- u = sigmoid(t @ wu^T + bu) ---------------------------------
__global__ void u_kernel(const float* __restrict__ wu, const float* __restrict__ bu,
                         float* __restrict__ dout_u) {
    int i = blockIdx.x * 8 + (threadIdx.x >> 5);
    int lane = threadIdx.x & 31;
    const float* t = g_t + (size_t)i * CCH;
    float s = 0.f;
    #pragma unroll
    for (int j = 0; j < 8; j++) s += t[lane + j * 32] * wu[lane + j * 32];
    #pragma unroll
    for (int o = 16; o; o >>= 1) s += __shfl_down_sync(~0u, s, o);
    if (lane == 0) {
        float uu = 1.f / (1.f + expf(-(s + bu[0])));
        g_u[i] = uu;
        dout_u[i] = uu;
    }
}

// ---------------- row softmax over 4096 keys ---------------------------------
__global__ void softmax_rows(float* __restrict__ S) {
    float4* p = (float4*)(S + (size_t)blockIdx.x * BHW);
    int tid = threadIdx.x;
    __shared__ float red[8];
    float m = -1e30f;
    for (int j = tid; j < BHW / 4; j += 256) {
        float4 v = p[j];
        m = fmaxf(fmaxf(fmaxf(m, v.x), v.y), fmaxf(v.z, v.w));
    }
    #pragma unroll
    for (int o = 16; o; o >>= 1) m = fmaxf(m, __shfl_xor_sync(~0u, m, o));
    if ((tid & 31) == 0) red[tid >> 5] = m;
    __syncthreads();
    m = fmaxf(fmaxf(fmaxf(red[0], red[1]), fmaxf(red[2], red[3])),
              fmaxf(fmaxf(red[4], red[5]), fmaxf(red[6], red[7])));
    __syncthreads();
    float s = 0.f;
    for (int j = tid; j < BHW / 4; j += 256) {
        float4 v = p[j];
        v.x = __expf(v.x - m); v.y = __expf(v.y - m);
        v.z = __expf(v.z - m); v.w = __expf(v.w - m);
        s += v.x + v.y + v.z + v.w;
        p[j] = v;
    }
    #pragma unroll
    for (int o = 16; o; o >>= 1) s += __shfl_xor_sync(~0u, s, o);
    if ((tid & 31) == 0) red[tid >> 5] = s;
    __syncthreads();
    s = red[0] + red[1] + red[2] + red[3] + red[4] + red[5] + red[6] + red[7];
    float inv = 1.f / s;
    for (int j = tid; j < BHW / 4; j += 256) {
        float4 v = p[j];
        v.x *= inv; v.y *= inv; v.z *= inv; v.w *= inv;
        p[j] = v;
    }
}

// ---------------- final: out = x + y^T (per batch), transpose ----------------
__global__ void final_out(const float* __restrict__ x, float* __restrict__ out) {
    __shared__ float tile[32][33];
    int b  = blockIdx.z;
    int c0 = blockIdx.y * 32;
    int s0 = blockIdx.x * 32;
    int tx = threadIdx.x, ty = threadIdx.y;
    for (int i = ty; i < 32; i += 8)
        tile[i][tx] = g_y[((size_t)(b * BHW + s0 + i)) * CCH + c0 + tx];
    __syncthreads();
    for (int i = ty; i < 32; i += 8) {
        size_t idx = ((size_t)(b * CCH + c0 + i)) * BHW + s0 + tx;
        out[idx] = x[idx] + tile[tx][i];
    }
}

// ---------------- launch -----------------------------------------------------
extern "C" void kernel_launch(void* const* d_in, const int* in_sizes, int n_in,
                              void* d_out, int out_size) {
    (void)in_sizes; (void)n_in; (void)out_size;
    const float* x     = (const float*)d_in[0];
    const float* gamma = (const float*)d_in[1];
    const float* beta  = (const float*)d_in[2];
    const float* wq    = (const float*)d_in[3];
    const float* bq    = (const float*)d_in[4];
    const float* wk    = (const float*)d_in[5];
    const float* bk    = (const float*)d_in[6];
    const float* wv    = (const float*)d_in[7];
    const float* bv    = (const float*)d_in[8];
    const float* wu    = (const float*)d_in[9];
    const float* bu    = (const float*)d_in[10];
    const float* wp    = (const float*)d_in[11];
    const float* bp    = (const float*)d_in[12];
    float* out = (float*)d_out;

    float *pt, *pq, *pk, *pv, *po, *py, *pu, *ps;
    cudaGetSymbolAddress((void**)&pt, g_t);
    cudaGetSymbolAddress((void**)&pq, g_q);
    cudaGetSymbolAddress((void**)&pk, g_k);
    cudaGetSymbolAddress((void**)&pv, g_v);
    cudaGetSymbolAddress((void**)&po, g_o);
    cudaGetSymbolAddress((void**)&py, g_y);
    cudaGetSymbolAddress((void**)&pu, g_u);
    cudaGetSymbolAddress((void**)&ps, g_s);

    // 1) GroupNorm
    gn_stats<<<NBAT * NGRP, 256>>>(x);
    gn_apply<<<dim3(BHW / 32, CCH / 32, NBAT), dim3(32, 8)>>>(x, gamma, beta);

    // 2) QKV projections: [16384,256] = t @ W^T + b
    gemm_tf32<0, 0><<<dim3(2, 128, 1), 256>>>(pt, wq, pq, 256, 256, bq, nullptr, 0.f, 0, 0, 0, 0);
    gemm_tf32<0, 0><<<dim3(2, 128, 1), 256>>>(pt, wk, pk, 256, 256, bk, nullptr, 0.f, 0, 0, 0, 0);
    gemm_tf32<0, 0><<<dim3(2, 128, 1), 256>>>(pt, wv, pv, 256, 256, bv, nullptr, 0.f, 0, 0, 0, 0);

    // 3) gate (also writes u_map part of output)
    u_kernel<<<NTOK / 8, 256>>>(wu, bu, out + OUT_MAIN);

    // 4) scores[b] = (q[b] @ k[b]^T) * scale * u[b, j]
    gemm_tf32<0, 1><<<dim3(32, 32, NBAT), 256>>>(pq, pk, ps, BHW, 256, nullptr, pu, 0.0625f,
                                                 (size_t)BHW * CCH, (size_t)BHW * CCH,
                                                 (size_t)BHW * BHW, (size_t)BHW);

    // 5) softmax over keys
    softmax_rows<<<NTOK, 256>>>(ps);

    // 6) out[b] = P[b] @ v[b]   (B non-transposed: [K=4096, N=256])
    gemm_tf32<1, 2><<<dim3(2, 32, NBAT), 256>>>(ps, pv, po, 256, BHW, nullptr, nullptr, 0.f,
                                                (size_t)BHW * BHW, (size_t)BHW * CCH,
                                                (size_t)BHW * CCH, 0);

    // 7) projection
    gemm_tf32<0, 0><<<dim3(2, 128, 1), 256>>>(po, wp, py, 256, 256, bp, nullptr, 0.f, 0, 0, 0, 0);

    // 8) residual + transpose back to [B,C,H,W]
    final_out<<<dim3(BHW / 32, CCH / 32, NBAT), dim3(32, 8)>>>(x, out);
}

// round 3
// speedup vs baseline: 1.0419x; 1.0371x over previous
#include <cuda_runtime.h>
#include <math.h>

// Problem constants
#define BHW   4096
#define CCH   256
#define NBAT  4
#define NTOK  16384
#define NGRP  32
#define GELEMS (8*BHW)
#define OUT_MAIN ((size_t)NBAT*CCH*BHW)

// ---------------- scratch ----------------------------------------------------
__device__ float g_t[(size_t)NTOK*CCH];     // normalized tokens [tok, c]
__device__ float g_qkv[(size_t)NTOK*768];   // fused qkv [tok, 768]
__device__ float g_o[(size_t)NTOK*CCH];     // attn output [tok, c]
__device__ float g_y[(size_t)NTOK*CCH];     // proj output [tok, c]
__device__ float g_u[NTOK];
__device__ float g_wqkv[768*256];
__device__ float g_bqkv[768];
__device__ float g_mu[NBAT*NGRP];
__device__ float g_rs[NBAT*NGRP];

// ---------------- GroupNorm stats -------------------------------------------
__global__ void gn_stats(const float* __restrict__ x) {
    int bg = blockIdx.x;
    const float4* p = (const float4*)(x + (size_t)bg * GELEMS);
    float s = 0.f, ss = 0.f;
    for (int i = threadIdx.x; i < GELEMS/4; i += blockDim.x) {
        float4 v = p[i];
        s  += v.x + v.y + v.z + v.w;
        ss += v.x*v.x + v.y*v.y + v.z*v.z + v.w*v.w;
    }
    __shared__ float rs[8], rss[8];
    #pragma unroll
    for (int o = 16; o; o >>= 1) { s += __shfl_down_sync(~0u, s, o); ss += __shfl_down_sync(~0u, ss, o); }
    if ((threadIdx.x & 31) == 0) { rs[threadIdx.x >> 5] = s; rss[threadIdx.x >> 5] = ss; }
    __syncthreads();
    if (threadIdx.x < 32) {
        s  = (threadIdx.x < 8) ? rs[threadIdx.x]  : 0.f;
        ss = (threadIdx.x < 8) ? rss[threadIdx.x] : 0.f;
        #pragma unroll
        for (int o = 4; o; o >>= 1) { s += __shfl_down_sync(~0u, s, o); ss += __shfl_down_sync(~0u, ss, o); }
        if (threadIdx.x == 0) {
            float mu  = s / (float)GELEMS;
            float var = ss / (float)GELEMS - mu * mu;
            g_mu[bg] = mu;
            g_rs[bg] = rsqrtf(var + 1e-6f);
        }
    }
}

// ---------------- normalize + transpose to [tok, c] --------------------------
__global__ void gn_apply(const float* __restrict__ x,
                         const float* __restrict__ gamma,
                         const float* __restrict__ beta) {
    __shared__ float tile[32][33];
    int b  = blockIdx.z;
    int c0 = blockIdx.y * 32;
    int s0 = blockIdx.x * 32;
    int tx = threadIdx.x, ty = threadIdx.y;
    for (int i = ty; i < 32; i += 8) {
        int c = c0 + i;
        int bg = b * NGRP + (c >> 3);
        float v = x[((size_t)(b * CCH + c)) * BHW + s0 + tx];
        tile[i][tx] = (v - g_mu[bg]) * g_rs[bg] * gamma[c] + beta[c];
    }
    __syncthreads();
    for (int i = ty; i < 32; i += 8)
        g_t[((size_t)(b * BHW + s0 + i)) * CCH + c0 + tx] = tile[tx][i];
}

// ---------------- pack qkv weights -------------------------------------------
__global__ void pack_w(const float* __restrict__ wq, const float* __restrict__ wk,
                       const float* __restrict__ wv, const float* __restrict__ bq,
                       const float* __restrict__ bk, const float* __restrict__ bv) {
    int r = blockIdx.x, tid = threadIdx.x;
    const float* w = (r < 256) ? wq : (r < 512) ? wk : wv;
    const float* bb = (r < 256) ? bq : (r < 512) ? bk : bv;
    int rr = r & 255;
    g_wqkv[r * 256 + tid] = w[rr * 256 + tid];
    if (tid == 0) g_bqkv[r] = bb[rr];
}

// ---------------- mma helper -------------------------------------------------
__device__ __forceinline__ void mma_tf32(float* c, const unsigned* a, const unsigned* b) {
    asm volatile("mma.sync.aligned.m16n8k8.row.col.f32.tf32.tf32.f32 "
                 "{%0,%1,%2,%3}, {%4,%5,%6,%7}, {%8,%9}, {%0,%1,%2,%3};"
                 : "+f"(c[0]), "+f"(c[1]), "+f"(c[2]), "+f"(c[3])
                 : "r"(a[0]), "r"(a[1]), "r"(a[2]), "r"(a[3]), "r"(b[0]), "r"(b[1]));
}
__device__ __forceinline__ unsigned fu(float f) { return __float_as_uint(f); }

// ---------------- cp.async helpers -------------------------------------------
__device__ __forceinline__ void cp16(float* smem, const float* g) {
    unsigned s = (unsigned)__cvta_generic_to_shared(smem);
    asm volatile("cp.async.cg.shared.global [%0], [%1], 16;" :: "r"(s), "l"(g));
}
#define CP_COMMIT asm volatile("cp.async.commit_group;")
#define CP_WAIT0  asm volatile("cp.async.wait_group 0;")

// ---------------- GEMM: C[M,N] = A[M,K] @ W[N,K]^T + bias --------------------
__global__ __launch_bounds__(256)
void gemm_tf32(const float* __restrict__ A, const float* __restrict__ Bm,
               float* __restrict__ Cp, int N, int K, const float* __restrict__ bias) {
    const int m0 = blockIdx.y * 128;
    const int n0 = blockIdx.x * 128;
    const int tid  = threadIdx.x;
    const int lane = tid & 31;
    const int warp = tid >> 5;
    const int wm = warp >> 1, wn = warp & 1;
    const int g  = lane >> 2, t4 = lane & 3;

    __shared__ float As[128 * 36];
    __shared__ float Bs[128 * 36];

    float acc[2][8][4];
    #pragma unroll
    for (int mi = 0; mi < 2; mi++)
        #pragma unroll
        for (int ni = 0; ni < 8; ni++)
            #pragma unroll
            for (int e = 0; e < 4; e++) acc[mi][ni][e] = 0.f;

    for (int kc = 0; kc < K; kc += 32) {
        #pragma unroll
        for (int it = 0; it < 4; it++) {
            int idx = tid + it * 256;
            int row = idx >> 3, seg = idx & 7;
            *(float4*)(As + row * 36 + seg * 4) =
                *(const float4*)(A + (size_t)(m0 + row) * K + kc + seg * 4);
            *(float4*)(Bs + row * 36 + seg * 4) =
                *(const float4*)(Bm + (size_t)(n0 + row) * K + kc + seg * 4);
        }
        __syncthreads();

        #pragma unroll
        for (int ks = 0; ks < 4; ks++) {
            const int k0 = ks * 8;
            unsigned af[2][4];
            #pragma unroll
            for (int mi = 0; mi < 2; mi++) {
                int r = wm * 32 + mi * 16 + g;
                af[mi][0] = fu(As[r * 36 + k0 + t4]);
                af[mi][1] = fu(As[(r + 8) * 36 + k0 + t4]);
                af[mi][2] = fu(As[r * 36 + k0 + t4 + 4]);
                af[mi][3] = fu(As[(r + 8) * 36 + k0 + t4 + 4]);
            }
            unsigned bf[8][2];
            #pragma unroll
            for (int ni = 0; ni < 8; ni++) {
                int cc = wn * 64 + ni * 8 + g;
                bf[ni][0] = fu(Bs[cc * 36 + k0 + t4]);
                bf[ni][1] = fu(Bs[cc * 36 + k0 + t4 + 4]);
            }
            #pragma unroll
            for (int mi = 0; mi < 2; mi++)
                #pragma unroll
                for (int ni = 0; ni < 8; ni++)
                    mma_tf32(acc[mi][ni], af[mi], bf[ni]);
        }
        __syncthreads();
    }

    #pragma unroll
    for (int mi = 0; mi < 2; mi++) {
        int rbase = m0 + wm * 32 + mi * 16 + g;
        #pragma unroll
        for (int ni = 0; ni < 8; ni++) {
            int cc = n0 + wn * 64 + ni * 8 + t4 * 2;
            #pragma unroll
            for (int half = 0; half < 2; half++) {
                int rr = rbase + half * 8;
                float2 w;
                w.x = acc[mi][ni][half * 2 + 0] + bias[cc];
                w.y = acc[mi][ni][half * 2 + 1] + bias[cc + 1];
                *(float2*)(Cp + (size_t)rr * N + cc) = w;
            }
        }
    }
}

// ---------------- u = sigmoid(t @ wu^T + bu) ---------------------------------
__global__ void u_kernel(const float* __restrict__ wu, const float* __restrict__ bu,
                         float* __restrict__ dout_u) {
    int i = blockIdx.x * 8 + (threadIdx.x >> 5);
    int lane = threadIdx.x & 31;
    const float* t = g_t + (size_t)i * CCH;
    float s = 0.f;
    #pragma unroll
    for (int j = 0; j < 8; j++) s += t[lane + j * 32] * wu[lane + j * 32];
    #pragma unroll
    for (int o = 16; o; o >>= 1) s += __shfl_down_sync(~0u, s, o);
    if (lane == 0) {
        float uu = 1.f / (1.f + expf(-(s + bu[0])));
        g_u[i] = uu;
        dout_u[i] = uu;
    }
}

// ---------------- fused flash attention --------------------------------------
// BM=64 queries/CTA, BN=64 keys/iter, d=256. 8 warps: (wm 0..3)x(wn 0..1).
#define QSTR 260
#define KSTR 260
#define VSTR 264
#define SSTR 68
#define SQ_OFF  0
#define SK_OFF  16640
#define SV_OFF  33280
#define SS_OFF  50176
#define SU_OFF  54528
#define SM_OFF  54592
#define SL_OFF  54656
#define SAL_OFF 54720
#define FLASH_SMEM (54784 * 4)

__global__ __launch_bounds__(256, 1)
void flash_attn(const float* __restrict__ qkv, const float* __restrict__ u,
                float* __restrict__ o) {
    extern __shared__ float sm[];
    float* sQ  = sm + SQ_OFF;
    float* sK  = sm + SK_OFF;
    float* sV  = sm + SV_OFF;
    float* sS  = sm + SS_OFF;
    float* sU  = sm + SU_OFF;
    float* sMx = sm + SM_OFF;
    float* sL  = sm + SL_OFF;
    float* sAl = sm + SAL_OFF;

    int b = blockIdx.y, q0 = blockIdx.x * 64;
    int tid = threadIdx.x, lane = tid & 31, warp = tid >> 5;
    int wm = warp >> 1, wn = warp & 1, g = lane >> 2, t4 = lane & 3;
    size_t tokb = (size_t)b * BHW;
    const float* Qg = qkv + (tokb + q0) * 768;
    const float* Kg = qkv + tokb * 768 + 256;
    const float* Vg = qkv + tokb * 768 + 512;
    const float* Ug = u + tokb;

    // stage Q, K[0], U[0]
    for (int i = tid; i < 4096; i += 256) {
        int r = i >> 6, s = i & 63;
        cp16(sQ + r * QSTR + s * 4, Qg + (size_t)r * 768 + s * 4);
    }
    for (int i = tid; i < 4096; i += 256) {
        int r = i >> 6, s = i & 63;
        cp16(sK + r * KSTR + s * 4, Kg + (size_t)r * 768 + s * 4);
    }
    if (tid < 16) cp16(sU + tid * 4, Ug + tid * 4);
    CP_COMMIT;

    if (tid < 64) { sMx[tid] = -1e30f; sL[tid] = 0.f; }
    float accO[16][4];
    #pragma unroll
    for (int ni = 0; ni < 16; ni++)
        #pragma unroll
        for (int e = 0; e < 4; e++) accO[ni][e] = 0.f;

    CP_WAIT0; __syncthreads();

    const int ar = (wm * 16 + g) * QSTR;
    const int sr = (wm * 16 + g) * SSTR;

    for (int it = 0; it < 64; ++it) {
        // prefetch V[it] (overlaps with QK compute)
        {
            const float* vs = Vg + (size_t)it * 64 * 768;
            for (int i = tid; i < 4096; i += 256) {
                int r = i >> 6, s = i & 63;
                cp16(sV + r * VSTR + s * 4, vs + (size_t)r * 768 + s * 4);
            }
            CP_COMMIT;
        }

        // S = Q @ K^T (per warp: 16 rows x 32 key-cols)
        float sacc[4][4];
        #pragma unroll
        for (int ni = 0; ni < 4; ni++)
            #pragma unroll
            for (int e = 0; e < 4; e++) sacc[ni][e] = 0.f;
        #pragma unroll
        for (int ks = 0; ks < 32; ks++) {
            int k0 = ks * 8;
            unsigned av[4];
            av[0] = fu(sQ[ar + k0 + t4]);
            av[1] = fu(sQ[ar + 8 * QSTR + k0 + t4]);
            av[2] = fu(sQ[ar + k0 + t4 + 4]);
            av[3] = fu(sQ[ar + 8 * QSTR + k0 + t4 + 4]);
            #pragma unroll
            for (int ni = 0; ni < 4; ni++) {
                int kc = (wn * 32 + ni * 8 + g) * KSTR;
                unsigned bv2[2] = { fu(sK[kc + k0 + t4]), fu(sK[kc + k0 + t4 + 4]) };
                mma_tf32(sacc[ni], av, bv2);
            }
        }

        CP_WAIT0;  // V[it] landed (this thread's copies; barrier below covers all)

        // scale by 1/16 * u[key], write S tile to smem
        #pragma unroll
        for (int ni = 0; ni < 4; ni++) {
            int c = wn * 32 + ni * 8 + t4 * 2;
            float u0 = sU[c] * 0.0625f, u1 = sU[c + 1] * 0.0625f;
            *(float2*)&sS[sr + c]            = make_float2(sacc[ni][0] * u0, sacc[ni][1] * u1);
            *(float2*)&sS[sr + 8 * SSTR + c] = make_float2(sacc[ni][2] * u0, sacc[ni][3] * u1);
        }
        __syncthreads();

        // online softmax: 4 threads per row, 16 cols each
        {
            int row = tid >> 2, sub = tid & 3;
            float* p = sS + row * SSTR + sub * 16;
            float4 v[4];
            #pragma unroll
            for (int j = 0; j < 4; j++) v[j] = *(float4*)(p + j * 4);
            float mt = -1e30f;
            #pragma unroll
            for (int j = 0; j < 4; j++)
                mt = fmaxf(mt, fmaxf(fmaxf(v[j].x, v[j].y), fmaxf(v[j].z, v[j].w)));
            mt = fmaxf(mt, __shfl_xor_sync(~0u, mt, 1));
            mt = fmaxf(mt, __shfl_xor_sync(~0u, mt, 2));
            float mo = sMx[row];
            float mn = fmaxf(mo, mt);
            float ls = 0.f;
            #pragma unroll
            for (int j = 0; j < 4; j++) {
                v[j].x = __expf(v[j].x - mn); v[j].y = __expf(v[j].y - mn);
                v[j].z = __expf(v[j].z - mn); v[j].w = __expf(v[j].w - mn);
                ls += v[j].x + v[j].y + v[j].z + v[j].w;
                *(float4*)(p + j * 4) = v[j];
            }
            ls += __shfl_xor_sync(~0u, ls, 1);
            ls += __shfl_xor_sync(~0u, ls, 2);
            if (sub == 0) {
                float al = __expf(mo - mn);
                sAl[row] = al;
                sL[row]  = sL[row] * al + ls;
                sMx[row] = mn;
            }
        }
        __syncthreads();

        // stage K[it+1] + U[it+1] (overlaps with PV compute)
        if (it + 1 < 64) {
            const float* ksrc = Kg + (size_t)(it + 1) * 64 * 768;
            for (int i = tid; i < 4096; i += 256) {
                int r = i >> 6, s = i & 63;
                cp16(sK + r * KSTR + s * 4, ksrc + (size_t)r * 768 + s * 4);
            }
            if (tid < 16) cp16(sU + tid * 4, Ug + (it + 1) * 64 + tid * 4);
            CP_COMMIT;
        }

        // rescale O, then O += P @ V (per warp: 16 rows x 128 d-cols)
        {
            int r0 = wm * 16 + g;
            float a0 = sAl[r0], a1 = sAl[r0 + 8];
            #pragma unroll
            for (int ni = 0; ni < 16; ni++) {
                accO[ni][0] *= a0; accO[ni][1] *= a0;
                accO[ni][2] *= a1; accO[ni][3] *= a1;
            }
            #pragma unroll
            for (int ks = 0; ks < 8; ks++) {
                int k0 = ks * 8;
                unsigned av[4];
                av[0] = fu(sS[sr + k0 + t4]);
                av[1] = fu(sS[sr + 8 * SSTR + k0 + t4]);
                av[2] = fu(sS[sr + k0 + t4 + 4]);
                av[3] = fu(sS[sr + 8 * SSTR + k0 + t4 + 4]);
                #pragma unroll
                for (int ni = 0; ni < 16; ni++) {
                    int c = wn * 128 + ni * 8 + g;
                    unsigned bv2[2] = { fu(sV[(k0 + t4) * VSTR + c]),
                                        fu(sV[(k0 + t4 + 4) * VSTR + c]) };
                    mma_tf32(accO[ni], av, bv2);
                }
            }
        }
        if (it + 1 < 64) { CP_WAIT0; }
        __syncthreads();
    }

    // epilogue: O /= l, write [tok, 256]
    int r0 = wm * 16 + g;
    float i0 = 1.f / sL[r0], i1 = 1.f / sL[r0 + 8];
    float* o0 = o + (tokb + q0 + r0) * 256;
    float* o1 = o + (tokb + q0 + r0 + 8) * 256;
    #pragma unroll
    for (int ni = 0; ni < 16; ni++) {
        int c = wn * 128 + ni * 8 + t4 * 2;
        *(float2*)&o0[c] = make_float2(accO[ni][0] * i0, accO[ni][1] * i0);
        *(float2*)&o1[c] = make_float2(accO[ni][2] * i1, accO[ni][3] * i1);
    }
}

// ---------------- final: out = x + y^T (per batch), transpose ----------------
__global__ void final_out(const float* __restrict__ x, float* __restrict__ out) {
    __shared__ float tile[32][33];
    int b  = blockIdx.z;
    int c0 = blockIdx.y * 32;
    int s0 = blockIdx.x * 32;
    int tx = threadIdx.x, ty = threadIdx.y;
    for (int i = ty; i < 32; i += 8)
        tile[i][tx] = g_y[((size_t)(b * BHW + s0 + i)) * CCH + c0 + tx];
    __syncthreads();
    for (int i = ty; i < 32; i += 8) {
        size_t idx = ((size_t)(b * CCH + c0 + i)) * BHW + s0 + tx;
        out[idx] = x[idx] + tile[tx][i];
    }
}

// ---------------- launch -----------------------------------------------------
extern "C" void kernel_launch(void* const* d_in, const int* in_sizes, int n_in,
                              void* d_out, int out_size) {
    (void)in_sizes; (void)n_in; (void)out_size;
    const float* x     = (const float*)d_in[0];
    const float* gamma = (const float*)d_in[1];
    const float* beta  = (const float*)d_in[2];
    const float* wq    = (const float*)d_in[3];
    const float* bq    = (const float*)d_in[4];
    const float* wk    = (const float*)d_in[5];
    const float* bk    = (const float*)d_in[6];
    const float* wv    = (const float*)d_in[7];
    const float* bv    = (const float*)d_in[8];
    const float* wu    = (const float*)d_in[9];
    const float* bu    = (const float*)d_in[10];
    const float* wp    = (const float*)d_in[11];
    const float* bp    = (const float*)d_in[12];
    float* out = (float*)d_out;

    float *pt, *pqkv, *po, *py, *pu, *pw, *pb;
    cudaGetSymbolAddress((void**)&pt,   g_t);
    cudaGetSymbolAddress((void**)&pqkv, g_qkv);
    cudaGetSymbolAddress((void**)&po,   g_o);
    cudaGetSymbolAddress((void**)&py,   g_y);
    cudaGetSymbolAddress((void**)&pu,   g_u);
    cudaGetSymbolAddress((void**)&pw,   g_wqkv);
    cudaGetSymbolAddress((void**)&pb,   g_bqkv);

    cudaFuncSetAttribute(flash_attn, cudaFuncAttributeMaxDynamicSharedMemorySize, FLASH_SMEM);

    // 1) GroupNorm
    gn_stats<<<NBAT * NGRP, 256>>>(x);
    gn_apply<<<dim3(BHW / 32, CCH / 32, NBAT), dim3(32, 8)>>>(x, gamma, beta);

    // 2) pack weights + fused QKV: [16384,768] = t @ Wqkv^T + b
    pack_w<<<768, 256>>>(wq, wk, wv, bq, bk, bv);
    gemm_tf32<<<dim3(6, 128), 256>>>(pt, pw, pqkv, 768, 256, pb);

    // 3) gate (also writes u_map part of output)
    u_kernel<<<NTOK / 8, 256>>>(wu, bu, out + OUT_MAIN);

    // 4) fused flash attention (scores + u-scale + softmax + PV)
    flash_attn<<<dim3(BHW / 64, NBAT), 256, FLASH_SMEM>>>(pqkv, pu, po);

    // 5) projection
    gemm_tf32<<<dim3(2, 128), 256>>>(po, wp, py, 256, 256, bp);

    // 6) residual + transpose back to [B,C,H,W]
    final_out<<<dim3(BHW / 32, CCH / 32, NBAT), dim3(32, 8)>>>(x, out);
}